// round 1
// baseline (speedup 1.0000x reference)
#include <cuda_runtime.h>

// Problem constants
#define NROWS   32768      // B * D*H*W = 8 * 4096 spatial positions
#define KCODES  2048
#define CDIM    256
#define ZQN     8388608    // 8*256*16*16*16
#define LOSS_OFF 8388608
#define IDX_OFF  8388609
#define NPART   8192

// Scratch (device globals — no allocation allowed)
__device__ float  g_se[KCODES];
__device__ float  g_sz[NROWS];
__device__ int    g_idx[NROWS];
__device__ double g_part[NPART];

// -------------------------------------------------------------------------
// Kernel 1: per-code squared norms  s_e[k] = sum_c emb[k,c]^2
// grid 16 x 128 threads, one code per thread (row-contiguous float4 reads)
// -------------------------------------------------------------------------
__global__ void k_se(const float* __restrict__ emb) {
    int k = blockIdx.x * 128 + threadIdx.x;
    const float4* e = (const float4*)(emb + (size_t)k * CDIM);
    float s = 0.f;
#pragma unroll 8
    for (int i = 0; i < CDIM / 4; i++) {
        float4 v = e[i];
        s += v.x * v.x;
        s += v.y * v.y;
        s += v.z * v.z;
        s += v.w * v.w;
    }
    g_se[k] = s;
}

// -------------------------------------------------------------------------
// Kernel 2: per-row squared norms  s_z[n] = sum_c z_flat[n,c]^2
// z layout [B,C,16,16,16]: z_flat[n,c] = z[b*1048576 + c*4096 + s],
// n = b*4096 + s.  Coalesced across warp (consecutive s).
// -------------------------------------------------------------------------
__global__ void k_sz(const float* __restrict__ z) {
    int n = blockIdx.x * 256 + threadIdx.x;
    int b = n >> 12, s = n & 4095;
    const float* p = z + (size_t)b * 1048576 + s;
    float acc = 0.f;
#pragma unroll 8
    for (int c = 0; c < CDIM; c++) {
        float v = p[(size_t)c * 4096];
        acc += v * v;
    }
    g_sz[n] = acc;
}

// -------------------------------------------------------------------------
// Kernel 3: distance GEMM + fused argmin.
// Each block: 64 rows x all 2048 codes, C=256 inner dim.
//  - full A slice (64 rows x 256 c) cached in smem as As[c][row] (64KB)
//  - B tiles (128 codes x 32 c) double-buffered, reg-staged, stored
//    transposed Bs[c][k] (stride 132 to reduce STS conflicts)
//  - 8x8 register microtile per thread (128 threads: tx 0..15 cols, ty 0..7 rows)
//  - dist = (s_z + s_e) - 2*dot  in fp32, exactly mirroring the reference's
//    rounding (the +||z||^2 term quantizes dists to ulp(256) — required to
//    reproduce the reference argmin including its rounding ties)
//  - ties broken toward lowest code index (jnp.argmin semantics)
// -------------------------------------------------------------------------
#define BS_STRIDE 132
#define BS_BUF (32 * BS_STRIDE)

__global__ __launch_bounds__(128, 2) void k_argmin(const float* __restrict__ z,
                                                   const float* __restrict__ emb) {
    extern __shared__ float sm[];
    float* As = sm;                 // [256][64]
    float* Bs = sm + 256 * 64;      // 2 x [32][BS_STRIDE]

    const int tid = threadIdx.x;
    const int tx = tid & 15, ty = tid >> 4;
    const int n0 = blockIdx.x * 64;
    const int b = n0 >> 12, s0 = n0 & 4095;
    const float* zb = z + (size_t)b * 1048576 + s0;

    // Load full A slice: As[c][row]  (coalesced: consecutive rows in memory)
#pragma unroll 4
    for (int i = 0; i < 128; i++) {
        int idx = tid + i * 128;          // 0..16383
        int row = idx & 63, c = idx >> 6;
        As[c * 64 + row] = zb[(size_t)c * 4096 + row];
    }

    float szr[8];
#pragma unroll
    for (int r = 0; r < 8; r++) szr[r] = g_sz[n0 + ty * 8 + r];

    __syncthreads();

    float bestd[8];
    int besti[8];
#pragma unroll
    for (int r = 0; r < 8; r++) { bestd[r] = 3.402823466e38f; besti[r] = 0; }

    for (int tile = 0; tile < 16; tile++) {
        const int k0 = tile * 128;
        float acc[8][8];
#pragma unroll
        for (int r = 0; r < 8; r++)
#pragma unroll
            for (int j = 0; j < 8; j++) acc[r][j] = 0.f;

        // stage chunk 0: 128 codes x 32 c = 1024 float4; 8 per thread
        float4 stg[8];
#pragma unroll
        for (int i = 0; i < 8; i++) {
            int u = tid + i * 128;
            int kk = u >> 3, m = u & 7;
            stg[i] = *(const float4*)(emb + (size_t)(k0 + kk) * 256 + m * 4);
        }

        int buf = 0;
        for (int ch = 0; ch < 8; ch++) {
            float* Bp = Bs + buf * BS_BUF;
            // transpose-store staged chunk into Bs[c][k]
#pragma unroll
            for (int i = 0; i < 8; i++) {
                int u = tid + i * 128;
                int kk = u >> 3, m = u & 7;
                Bp[(m * 4 + 0) * BS_STRIDE + kk] = stg[i].x;
                Bp[(m * 4 + 1) * BS_STRIDE + kk] = stg[i].y;
                Bp[(m * 4 + 2) * BS_STRIDE + kk] = stg[i].z;
                Bp[(m * 4 + 3) * BS_STRIDE + kk] = stg[i].w;
            }
            // prefetch next chunk into regs (latency overlaps compute below)
            if (ch < 7) {
#pragma unroll
                for (int i = 0; i < 8; i++) {
                    int u = tid + i * 128;
                    int kk = u >> 3, m = u & 7;
                    stg[i] = *(const float4*)(emb + (size_t)(k0 + kk) * 256 +
                                              (ch + 1) * 32 + m * 4);
                }
            }
            __syncthreads();

            const float* Ap = As + ch * 32 * 64;
#pragma unroll 8
            for (int c = 0; c < 32; c++) {
                float4 a0 = *(const float4*)(Ap + c * 64 + ty * 8);
                float4 a1 = *(const float4*)(Ap + c * 64 + ty * 8 + 4);
                float4 b0 = *(const float4*)(Bp + c * BS_STRIDE + tx * 8);
                float4 b1 = *(const float4*)(Bp + c * BS_STRIDE + tx * 8 + 4);
                float av[8] = {a0.x, a0.y, a0.z, a0.w, a1.x, a1.y, a1.z, a1.w};
                float bv[8] = {b0.x, b0.y, b0.z, b0.w, b1.x, b1.y, b1.z, b1.w};
#pragma unroll
                for (int r = 0; r < 8; r++)
#pragma unroll
                    for (int j = 0; j < 8; j++)
                        acc[r][j] += av[r] * bv[j];
            }
            buf ^= 1;
            // single sync per chunk is safe: a thread issuing STS into buffer X
            // has passed the sync that every thread only reaches after finishing
            // its previous compute on X.
        }

        // epilogue for this col-tile: dist + running argmin
#pragma unroll
        for (int j = 0; j < 8; j++) {
            int kk = k0 + tx * 8 + j;
            float se = g_se[kk];
#pragma unroll
            for (int r = 0; r < 8; r++) {
                float t1 = szr[r] + se;
                float d = t1 - 2.0f * acc[r][j];
                if (d < bestd[r]) { bestd[r] = d; besti[r] = kk; }
            }
        }
    }

    // cross-thread (tx) argmin reduction, lexicographic (dist, idx) min
    __syncthreads();
    float* rd = sm;                      // [64][16]
    int* ri = (int*)(sm + 64 * 16);
#pragma unroll
    for (int r = 0; r < 8; r++) {
        rd[(ty * 8 + r) * 16 + tx] = bestd[r];
        ri[(ty * 8 + r) * 16 + tx] = besti[r];
    }
    __syncthreads();
    if (tid < 64) {
        float bd = rd[tid * 16];
        int bi = ri[tid * 16];
#pragma unroll
        for (int t = 1; t < 16; t++) {
            float d = rd[tid * 16 + t];
            int i2 = ri[tid * 16 + t];
            if (d < bd || (d == bd && i2 < bi)) { bd = d; bi = i2; }
        }
        g_idx[n0 + tid] = bi;
    }
}

// -------------------------------------------------------------------------
// Kernel 4: gather codes, write z_q_st, accumulate loss partials.
// Output element j pairs gathered[j/256][j%256] with z.ravel()[j]
// (the reference reshapes the gather directly onto z.shape).
// z_q_st written as z + (zq - z) to mirror reference rounding exactly.
// -------------------------------------------------------------------------
__global__ void k_gather(const float* __restrict__ z, const float* __restrict__ emb,
                         float* __restrict__ out) {
    int t = blockIdx.x * 256 + threadIdx.x;
    int j0 = t * 4;
    int n = j0 >> 8;
    int c = j0 & 255;
    int id = g_idx[n];
    float4 e = *(const float4*)(emb + (size_t)id * 256 + c);
    float4 zv = *(const float4*)(z + j0);

    float dx = e.x - zv.x, dy = e.y - zv.y, dz = e.z - zv.z, dw = e.w - zv.w;
    float4 o;
    o.x = zv.x + dx; o.y = zv.y + dy; o.z = zv.z + dz; o.w = zv.w + dw;
    *(float4*)(out + j0) = o;

    double ls = (double)dx * dx + (double)dy * dy + (double)dz * dz + (double)dw * dw;

    __shared__ double red[256];
    red[threadIdx.x] = ls;
    __syncthreads();
    for (int s = 128; s > 0; s >>= 1) {
        if (threadIdx.x < s) red[threadIdx.x] += red[threadIdx.x + s];
        __syncthreads();
    }
    if (threadIdx.x == 0) g_part[blockIdx.x] = red[0];
}

// -------------------------------------------------------------------------
// Kernel 5: finalize loss + write idx as float
// vq_loss = m + 0.25*m  (codebook and commitment losses are numerically equal)
// -------------------------------------------------------------------------
__global__ void k_final(float* __restrict__ out) {
    __shared__ double red[256];
    int tid = threadIdx.x;
    double s = 0.0;
    for (int i = tid; i < NPART; i += 256) s += g_part[i];
    red[tid] = s;
    __syncthreads();
    for (int st = 128; st > 0; st >>= 1) {
        if (tid < st) red[tid] += red[tid + st];
        __syncthreads();
    }
    if (tid == 0) {
        float m = (float)(red[0] / (double)ZQN);
        out[LOSS_OFF] = m + 0.25f * m;
    }
    for (int i = tid; i < NROWS; i += 256) out[IDX_OFF + i] = (float)g_idx[i];
}

// -------------------------------------------------------------------------
extern "C" void kernel_launch(void* const* d_in, const int* in_sizes, int n_in,
                              void* d_out, int out_size) {
    const float* z = (const float*)d_in[0];
    const float* emb = (const float*)d_in[1];
    float* out = (float*)d_out;

    k_se<<<16, 128>>>(emb);
    k_sz<<<128, 256>>>(z);

    int shmem = (256 * 64 + 2 * BS_BUF) * (int)sizeof(float);   // 99,328 B
    cudaFuncSetAttribute(k_argmin, cudaFuncAttributeMaxDynamicSharedMemorySize, shmem);
    k_argmin<<<512, 128, shmem>>>(z, emb);

    k_gather<<<NPART, 256>>>(z, emb, out);
    k_final<<<1, 256>>>(out);
}

// round 3
// speedup vs baseline: 1.6514x; 1.6514x over previous
#include <cuda_runtime.h>

// Problem constants
#define NROWS   32768      // B * D*H*W = 8 * 4096 spatial positions
#define KCODES  2048
#define CDIM    256
#define ZQN     8388608    // 8*256*16*16*16
#define LOSS_OFF 8388608
#define IDX_OFF  8388609
#define NPART   4096

typedef unsigned long long u64;

// Scratch (device globals — no allocation allowed)
__device__ float  g_se[KCODES];
__device__ float  g_sz[NROWS];
__device__ int    g_idx[NROWS];
__device__ double g_part[NPART];

// ---- packed f32x2 helpers (Blackwell FFMA2 path; each lane is IEEE fp32 RN,
//      bit-identical to scalar FFMA, so argmin numerics are unchanged) -------
__device__ __forceinline__ u64 pack2(float lo, float hi) {
    u64 r;
    asm("mov.b64 %0, {%1, %2};" : "=l"(r)
        : "r"(__float_as_uint(lo)), "r"(__float_as_uint(hi)));
    return r;
}
__device__ __forceinline__ void unpack2(u64 v, float& lo, float& hi) {
    unsigned a, b;
    asm("mov.b64 {%0, %1}, %2;" : "=r"(a), "=r"(b) : "l"(v));
    lo = __uint_as_float(a); hi = __uint_as_float(b);
}
__device__ __forceinline__ void ffma2(u64& acc, u64 a, u64 b) {
    asm("fma.rn.f32x2 %0, %1, %2, %0;" : "+l"(acc) : "l"(a), "l"(b));
}

// -------------------------------------------------------------------------
// Kernel 1: per-code squared norms
// -------------------------------------------------------------------------
__global__ void k_se(const float* __restrict__ emb) {
    int k = blockIdx.x * 128 + threadIdx.x;
    const float4* e = (const float4*)(emb + (size_t)k * CDIM);
    float s = 0.f;
#pragma unroll 8
    for (int i = 0; i < CDIM / 4; i++) {
        float4 v = e[i];
        s += v.x * v.x; s += v.y * v.y; s += v.z * v.z; s += v.w * v.w;
    }
    g_se[k] = s;
}

// -------------------------------------------------------------------------
// Kernel 2: per-row squared norms (z layout [B,C,16,16,16], coalesced in s)
// -------------------------------------------------------------------------
__global__ void k_sz(const float* __restrict__ z) {
    int n = blockIdx.x * 256 + threadIdx.x;
    int b = n >> 12, s = n & 4095;
    const float* p = z + (size_t)b * 1048576 + s;
    float acc = 0.f;
#pragma unroll 8
    for (int c = 0; c < CDIM; c++) {
        float v = p[(size_t)c * 4096];
        acc += v * v;
    }
    g_sz[n] = acc;
}

// -------------------------------------------------------------------------
// Kernel 3: distance GEMM + fused argmin, FFMA2 mainloop.
// Block: 64 rows x 2048 codes. As[c][row] 64KB resident; B double-buffered
// reg-staged + transposed. 8x8 per-thread microtile computed as 4x4 grid of
// 2x2 pair-blocks: column pairs are the free 64-bit halves of LDS.128,
// row side needs 4 natural + 4 swapped packs per c.
//   accA[p][q] = ((2p,2q),(2p+1,2q+1))   via (a2p,a2p+1)*(b2q,b2q+1)
//   accB[p][q] = ((2p+1,2q),(2p,2q+1))   via (a2p+1,a2p)*(b2q,b2q+1)
// Per-scalar accumulation sequence identical to R1 kernel.
// -------------------------------------------------------------------------
#define BS_STRIDE 132
#define BS_BUF (32 * BS_STRIDE)

__global__ __launch_bounds__(128, 2) void k_argmin(const float* __restrict__ z,
                                                   const float* __restrict__ emb) {
    extern __shared__ float sm[];
    float* As = sm;                 // [256][64]
    float* Bs = sm + 256 * 64;      // 2 x [32][BS_STRIDE]

    const int tid = threadIdx.x;
    const int tx = tid & 15, ty = tid >> 4;
    const int n0 = blockIdx.x * 64;
    const int b = n0 >> 12, s0 = n0 & 4095;
    const float* zb = z + (size_t)b * 1048576 + s0;

#pragma unroll 4
    for (int i = 0; i < 128; i++) {
        int idx = tid + i * 128;
        int row = idx & 63, c = idx >> 6;
        As[c * 64 + row] = zb[(size_t)c * 4096 + row];
    }

    float szr[8];
#pragma unroll
    for (int r = 0; r < 8; r++) szr[r] = g_sz[n0 + ty * 8 + r];

    __syncthreads();

    float bestd[8];
    int besti[8];
#pragma unroll
    for (int r = 0; r < 8; r++) { bestd[r] = 3.402823466e38f; besti[r] = 0; }

    for (int tile = 0; tile < 16; tile++) {
        const int k0 = tile * 128;
        u64 accA[4][4], accB[4][4];
#pragma unroll
        for (int p = 0; p < 4; p++)
#pragma unroll
            for (int q = 0; q < 4; q++) { accA[p][q] = 0ull; accB[p][q] = 0ull; }

        // stage chunk 0
        float4 stg[8];
#pragma unroll
        for (int i = 0; i < 8; i++) {
            int u = tid + i * 128;
            int kk = u >> 3, m = u & 7;
            stg[i] = *(const float4*)(emb + (size_t)(k0 + kk) * 256 + m * 4);
        }

        int buf = 0;
        for (int ch = 0; ch < 8; ch++) {
            float* Bp = Bs + buf * BS_BUF;
#pragma unroll
            for (int i = 0; i < 8; i++) {
                int u = tid + i * 128;
                int kk = u >> 3, m = u & 7;
                Bp[(m * 4 + 0) * BS_STRIDE + kk] = stg[i].x;
                Bp[(m * 4 + 1) * BS_STRIDE + kk] = stg[i].y;
                Bp[(m * 4 + 2) * BS_STRIDE + kk] = stg[i].z;
                Bp[(m * 4 + 3) * BS_STRIDE + kk] = stg[i].w;
            }
            if (ch < 7) {
#pragma unroll
                for (int i = 0; i < 8; i++) {
                    int u = tid + i * 128;
                    int kk = u >> 3, m = u & 7;
                    stg[i] = *(const float4*)(emb + (size_t)(k0 + kk) * 256 +
                                              (ch + 1) * 32 + m * 4);
                }
            }
            __syncthreads();

            const float* Ap = As + ch * 32 * 64;
#pragma unroll 4
            for (int c = 0; c < 32; c++) {
                float4 a0 = *(const float4*)(Ap + c * 64 + ty * 8);
                float4 a1 = *(const float4*)(Ap + c * 64 + ty * 8 + 4);
                ulonglong2 b0 = *(const ulonglong2*)(Bp + c * BS_STRIDE + tx * 8);
                ulonglong2 b1 = *(const ulonglong2*)(Bp + c * BS_STRIDE + tx * 8 + 4);
                u64 bq[4] = {b0.x, b0.y, b1.x, b1.y};
                float ar[8] = {a0.x, a0.y, a0.z, a0.w, a1.x, a1.y, a1.z, a1.w};
                u64 an[4], asw[4];
#pragma unroll
                for (int p = 0; p < 4; p++) {
                    an[p]  = pack2(ar[2 * p],     ar[2 * p + 1]);
                    asw[p] = pack2(ar[2 * p + 1], ar[2 * p]);
                }
#pragma unroll
                for (int p = 0; p < 4; p++)
#pragma unroll
                    for (int q = 0; q < 4; q++) {
                        ffma2(accA[p][q], an[p],  bq[q]);
                        ffma2(accB[p][q], asw[p], bq[q]);
                    }
            }
            buf ^= 1;
        }

        // unpack pair-blocks back to the scalar 8x8 microtile
        float acc[8][8];
#pragma unroll
        for (int p = 0; p < 4; p++)
#pragma unroll
            for (int q = 0; q < 4; q++) {
                float lo, hi;
                unpack2(accA[p][q], lo, hi);
                acc[2 * p][2 * q] = lo; acc[2 * p + 1][2 * q + 1] = hi;
                unpack2(accB[p][q], lo, hi);
                acc[2 * p + 1][2 * q] = lo; acc[2 * p][2 * q + 1] = hi;
            }

        // epilogue: dist + running argmin (identical math to R1)
#pragma unroll
        for (int j = 0; j < 8; j++) {
            int kk = k0 + tx * 8 + j;
            float se = g_se[kk];
#pragma unroll
            for (int r = 0; r < 8; r++) {
                float t1 = szr[r] + se;
                float d = t1 - 2.0f * acc[r][j];
                if (d < bestd[r]) { bestd[r] = d; besti[r] = kk; }
            }
        }
    }

    // cross-thread argmin reduction, lexicographic (dist, idx) min
    __syncthreads();
    float* rd = sm;
    int* ri = (int*)(sm + 64 * 16);
#pragma unroll
    for (int r = 0; r < 8; r++) {
        rd[(ty * 8 + r) * 16 + tx] = bestd[r];
        ri[(ty * 8 + r) * 16 + tx] = besti[r];
    }
    __syncthreads();
    if (tid < 64) {
        float bd = rd[tid * 16];
        int bi = ri[tid * 16];
#pragma unroll
        for (int t = 1; t < 16; t++) {
            float d = rd[tid * 16 + t];
            int i2 = ri[tid * 16 + t];
            if (d < bd || (d == bd && i2 < bi)) { bd = d; bi = i2; }
        }
        g_idx[n0 + tid] = bi;
    }
}

// -------------------------------------------------------------------------
// Kernel 4: gather + z_q_st + loss partials. One warp per row: idx loaded
// once (L1 broadcast), emb row fully coalesced, shuffle reduction, one
// partial per block (no atomics -> deterministic).
// -------------------------------------------------------------------------
__global__ __launch_bounds__(256) void k_gather(const float* __restrict__ z,
                                                const float* __restrict__ emb,
                                                float* __restrict__ out) {
    const int tid = threadIdx.x;
    const int lane = tid & 31, w = tid >> 5;
    const int n = blockIdx.x * 8 + w;
    const int id = g_idx[n];                 // uniform per warp, L1 broadcast
    const size_t eo = (size_t)id * 256 + lane * 8;
    const size_t zo = (size_t)n * 256 + lane * 8;

    float4 e0 = *(const float4*)(emb + eo);
    float4 e1 = *(const float4*)(emb + eo + 4);
    float4 z0 = *(const float4*)(z + zo);
    float4 z1 = *(const float4*)(z + zo + 4);

    float d0 = e0.x - z0.x, d1 = e0.y - z0.y, d2 = e0.z - z0.z, d3 = e0.w - z0.w;
    float d4 = e1.x - z1.x, d5 = e1.y - z1.y, d6 = e1.z - z1.z, d7 = e1.w - z1.w;

    float4 o0, o1;
    o0.x = z0.x + d0; o0.y = z0.y + d1; o0.z = z0.z + d2; o0.w = z0.w + d3;
    o1.x = z1.x + d4; o1.y = z1.y + d5; o1.z = z1.z + d6; o1.w = z1.w + d7;
    *(float4*)(out + zo) = o0;
    *(float4*)(out + zo + 4) = o1;

    double s = (double)d0 * d0 + (double)d1 * d1 + (double)d2 * d2 + (double)d3 * d3
             + (double)d4 * d4 + (double)d5 * d5 + (double)d6 * d6 + (double)d7 * d7;

#pragma unroll
    for (int off = 16; off > 0; off >>= 1)
        s += __shfl_down_sync(0xffffffffu, s, off);

    __shared__ double sp[8];
    if (lane == 0) sp[w] = s;
    __syncthreads();
    if (tid == 0) {
        double t = 0.0;
#pragma unroll
        for (int i = 0; i < 8; i++) t += sp[i];
        g_part[blockIdx.x] = t;
    }
}

// -------------------------------------------------------------------------
// Kernel 5: finalize loss + write idx as float
// -------------------------------------------------------------------------
__global__ void k_final(float* __restrict__ out) {
    __shared__ double red[256];
    int tid = threadIdx.x;
    double s = 0.0;
    for (int i = tid; i < NPART; i += 256) s += g_part[i];
    red[tid] = s;
    __syncthreads();
    for (int st = 128; st > 0; st >>= 1) {
        if (tid < st) red[tid] += red[tid + st];
        __syncthreads();
    }
    if (tid == 0) {
        float m = (float)(red[0] / (double)ZQN);
        out[LOSS_OFF] = m + 0.25f * m;
    }
    for (int i = tid; i < NROWS; i += 256) out[IDX_OFF + i] = (float)g_idx[i];
}

// -------------------------------------------------------------------------
extern "C" void kernel_launch(void* const* d_in, const int* in_sizes, int n_in,
                              void* d_out, int out_size) {
    const float* z = (const float*)d_in[0];
    const float* emb = (const float*)d_in[1];
    float* out = (float*)d_out;

    k_se<<<16, 128>>>(emb);
    k_sz<<<128, 256>>>(z);

    int shmem = (256 * 64 + 2 * BS_BUF) * (int)sizeof(float);   // 99,328 B
    cudaFuncSetAttribute(k_argmin, cudaFuncAttributeMaxDynamicSharedMemorySize, shmem);
    k_argmin<<<512, 128, shmem>>>(z, emb);

    k_gather<<<NPART, 256>>>(z, emb, out);
    k_final<<<1, 256>>>(out);
}